// round 2
// baseline (speedup 1.0000x reference)
#include <cuda_runtime.h>
#include <math.h>

#define BB    64      // batch (GEMM M)
#define TTT   512     // timesteps
#define FIN_  256     // x features
#define HH    1024    // hidden
#define OUTD  64      // output dim
#define GRID  128     // persistent blocks
#define NTHR  256     // threads per block
#define KTT   16      // K tile
#define HB    (HH*BB) // 65536

// ---------------- global scratch (static device memory; no allocs) ----------
__device__ __align__(16) float g_actA[HB];     // e1 / d1
__device__ __align__(16) float g_actB[HB];     // e2 / d2
__device__ __align__(16) float g_actR[HB];     // r = relu(e)
__device__ __align__(16) float g_h[HB];        // LSTM h, layout [j][b]
__device__ __align__(16) float g_c[HB];        // LSTM c, layout [j][b]
__device__ __align__(16) float g_part[8*HB];   // split-K partials (8 MB)
__device__ __align__(16) float g_ycur[OUTD*BB];  // y   , layout [j][b]
__device__ __align__(16) float g_yprev[OUTD*BB]; // y_prev, layout [j][b]
__device__ unsigned g_bar;

__device__ __forceinline__ float sigm(float v){ return 1.0f/(1.0f + expf(-v)); }

// ---------------- device-wide barrier (all GRID blocks co-resident) ---------
__device__ __forceinline__ void grid_barrier(unsigned &target){
    __syncthreads();
    __threadfence();          // release: make this thread's global writes visible
    __syncthreads();          // all fences done before arrive
    if (threadIdx.x == 0){
        atomicAdd(&g_bar, 1u);
        while (*(volatile unsigned*)&g_bar < target) { }
        __threadfence();      // acquire: CCTL.IVALL -> invalidate stale L1 lines
    }
    __syncthreads();
    target += GRID;
}

// ---------------- 64x64 tile GEMM core --------------------------------------
// A layout: [k][m], m contiguous (64). W layout: row-major [k][n], ld = ldw.
__device__ __forceinline__ void compute_tile(float acc[4][4],
        const float (* __restrict__ As)[BB], const float (* __restrict__ Ws)[64],
        int ty, int tx)
{
#pragma unroll
    for (int k = 0; k < KTT; k++){
        float4 a = *(const float4*)&As[k][ty << 2];
        float4 w = *(const float4*)&Ws[k][tx << 2];
        acc[0][0] = fmaf(a.x, w.x, acc[0][0]);
        acc[0][1] = fmaf(a.x, w.y, acc[0][1]);
        acc[0][2] = fmaf(a.x, w.z, acc[0][2]);
        acc[0][3] = fmaf(a.x, w.w, acc[0][3]);
        acc[1][0] = fmaf(a.y, w.x, acc[1][0]);
        acc[1][1] = fmaf(a.y, w.y, acc[1][1]);
        acc[1][2] = fmaf(a.y, w.z, acc[1][2]);
        acc[1][3] = fmaf(a.y, w.w, acc[1][3]);
        acc[2][0] = fmaf(a.z, w.x, acc[2][0]);
        acc[2][1] = fmaf(a.z, w.y, acc[2][1]);
        acc[2][2] = fmaf(a.z, w.z, acc[2][2]);
        acc[2][3] = fmaf(a.z, w.w, acc[2][3]);
        acc[3][0] = fmaf(a.w, w.x, acc[3][0]);
        acc[3][1] = fmaf(a.w, w.y, acc[3][1]);
        acc[3][2] = fmaf(a.w, w.z, acc[3][2]);
        acc[3][3] = fmaf(a.w, w.w, acc[3][3]);
    }
}

// Generic tile job: C[64 x 64] = A[k0:k0+kc][0:64] * W[k0:k0+kc][n0:n0+64]
// writes raw partial (no bias/act) to outp with layout [n][m].
template<bool RELU_A>
__device__ __forceinline__ void gemm_tile(
    const float* __restrict__ A, const float* __restrict__ W, int ldw,
    int n0, int k0, int kc, float* __restrict__ outp,
    float (*As)[BB], float (*Ws)[64], int tid, int ty, int tx)
{
    float acc[4][4] = {{0.f,0.f,0.f,0.f},{0.f,0.f,0.f,0.f},
                       {0.f,0.f,0.f,0.f},{0.f,0.f,0.f,0.f}};
    for (int kb = 0; kb < kc; kb += KTT){
        int k  = tid >> 4;
        int m4 = (tid & 15) << 2;
        float4 v = *(const float4*)(A + (size_t)(k0 + kb + k)*BB + m4);
        if (RELU_A){
            v.x = fmaxf(v.x, 0.f); v.y = fmaxf(v.y, 0.f);
            v.z = fmaxf(v.z, 0.f); v.w = fmaxf(v.w, 0.f);
        }
        *(float4*)&As[k][m4] = v;
        *(float4*)&Ws[k][m4] = *(const float4*)(W + (size_t)(k0 + kb + k)*ldw + n0 + m4);
        __syncthreads();
        compute_tile(acc, (const float(*)[BB])As, (const float(*)[64])Ws, ty, tx);
        __syncthreads();
    }
    int m0 = ty << 2, nb = n0 + (tx << 2);
#pragma unroll
    for (int j = 0; j < 4; j++){
        float4 v = make_float4(acc[0][j], acc[1][j], acc[2][j], acc[3][j]);
        *(float4*)(outp + (size_t)(nb + j)*BB + m0) = v;
    }
}

// Stage 1: e1 = relu([x_t, y, y_prev] @ W_e_in + b_e_in) -> g_actA. K = 384.
__device__ __forceinline__ void stage1(
    const float* __restrict__ x, const float* __restrict__ W_e_in,
    const float* __restrict__ b_e_in,
    int t, int n0, float (*As)[BB], float (*Ws)[64], int tid, int ty, int tx)
{
    float acc[4][4] = {{0.f,0.f,0.f,0.f},{0.f,0.f,0.f,0.f},
                       {0.f,0.f,0.f,0.f},{0.f,0.f,0.f,0.f}};
    for (int kb = 0; kb < 384; kb += KTT){
        if (kb < FIN_){
            // x slice: As[k][m] = x[m][t][kb+k]
            int m  = tid >> 2;
            int kq = (tid & 3) << 2;
            float4 v = *(const float4*)(x + (size_t)m*TTT*FIN_ + (size_t)t*FIN_ + kb + kq);
            As[kq+0][m] = v.x; As[kq+1][m] = v.y;
            As[kq+2][m] = v.z; As[kq+3][m] = v.w;
        } else {
            const float* src = (kb < 320) ? g_ycur : g_yprev;
            int base = (kb < 320) ? (kb - 256) : (kb - 320);
            int k  = tid >> 4;
            int m4 = (tid & 15) << 2;
            *(float4*)&As[k][m4] = *(const float4*)(src + (size_t)(base + k)*BB + m4);
        }
        {
            int k  = tid >> 4;
            int n4 = (tid & 15) << 2;
            *(float4*)&Ws[k][n4] = *(const float4*)(W_e_in + (size_t)(kb + k)*HH + n0 + n4);
        }
        __syncthreads();
        compute_tile(acc, (const float(*)[BB])As, (const float(*)[64])Ws, ty, tx);
        __syncthreads();
    }
    int m0 = ty << 2, nb = n0 + (tx << 2);
#pragma unroll
    for (int j = 0; j < 4; j++){
        float bn = b_e_in[nb + j];
        float4 v = make_float4(fmaxf(acc[0][j] + bn, 0.f), fmaxf(acc[1][j] + bn, 0.f),
                               fmaxf(acc[2][j] + bn, 0.f), fmaxf(acc[3][j] + bn, 0.f));
        *(float4*)(g_actA + (size_t)(nb + j)*BB + m0) = v;
    }
}

// ---------------- init kernel (runs before persistent kernel each replay) ---
__global__ void init_kernel(const float* __restrict__ y0, const float* __restrict__ y1){
    int i = blockIdx.x * blockDim.x + threadIdx.x;
    int n = gridDim.x * blockDim.x;
    if (i == 0) g_bar = 0u;
    for (int idx = i; idx < HB; idx += n){ g_h[idx] = 0.f; g_c[idx] = 0.f; }
    for (int idx = i; idx < OUTD*BB; idx += n){
        int j = idx >> 6, b = idx & 63;
        g_ycur[idx]  = y1[b*OUTD + j];
        g_yprev[idx] = y0[b*OUTD + j];
    }
}

// ---------------- persistent RNN kernel -------------------------------------
__global__ void __launch_bounds__(NTHR)
rnn_kernel(const float* __restrict__ x, const int* __restrict__ x_len,
           const float* __restrict__ W_e_in,  const float* __restrict__ b_e_in,
           const float* __restrict__ W_e_h,   const float* __restrict__ b_e_h,
           const float* __restrict__ W_e_out, const float* __restrict__ b_e_out,
           const float* __restrict__ W_ih,    const float* __restrict__ W_hh,
           const float* __restrict__ b_ih,    const float* __restrict__ b_hh,
           const float* __restrict__ W_o_in,  const float* __restrict__ b_o_in,
           const float* __restrict__ W_o_h,   const float* __restrict__ b_o_h,
           const float* __restrict__ W_o_out, const float* __restrict__ b_o_out,
           float* __restrict__ out)
{
    __shared__ __align__(16) float As[KTT][BB];
    __shared__ __align__(16) float Ws[KTT][64];

    const int tid = threadIdx.x;
    const int bid = blockIdx.x;
    const int tx = tid & 15, ty = tid >> 4;
    const int gtid = bid * NTHR + tid;
    unsigned target = GRID;

    float* __restrict__ ys_out   = out;
    float* __restrict__ skip_out = out + (size_t)BB*TTT*OUTD;

    for (int t = 0; t < TTT; t++){
        // ---- S1: e1 (16 jobs, K=384) ----
        if (bid < 16)
            stage1(x, W_e_in, b_e_in, t, bid*64, As, Ws, tid, ty, tx);
        grid_barrier(target);

        // ---- S2: e2 partials = e1 @ W_e_h (16 n-tiles x 8 K-splits) ----
        {
            int nt = bid & 15, ks = bid >> 4;
            gemm_tile<false>(g_actA, W_e_h, HH, nt*64, ks*128, 128,
                             g_part + (size_t)ks*HB, As, Ws, tid, ty, tx);
        }
        grid_barrier(target);

        // ---- S2r: e2 = relu(sum + b_e_h) ----
        for (int idx = gtid; idx < HB; idx += GRID*NTHR){
            float s = 0.f;
#pragma unroll
            for (int p = 0; p < 8; p++) s += g_part[(size_t)p*HB + idx];
            g_actB[idx] = fmaxf(s + b_e_h[idx >> 6], 0.f);
        }
        grid_barrier(target);

        // ---- S3: e partials = e2 @ W_e_out ----
        {
            int nt = bid & 15, ks = bid >> 4;
            gemm_tile<false>(g_actB, W_e_out, HH, nt*64, ks*128, 128,
                             g_part + (size_t)ks*HB, As, Ws, tid, ty, tx);
        }
        grid_barrier(target);

        // ---- S3r: e = sum + b_e_out ; store skip (masked) ; r = relu(e) ----
        for (int idx = gtid; idx < HB; idx += GRID*NTHR){
            float s = 0.f;
#pragma unroll
            for (int p = 0; p < 8; p++) s += g_part[(size_t)p*HB + idx];
            int n = idx >> 6, m = idx & 63;
            float e = s + b_e_out[n];
            skip_out[((size_t)m*TTT + t)*HH + n] = (t < x_len[m]) ? e : 0.f;
            g_actR[idx] = fmaxf(e, 0.f);
        }
        grid_barrier(target);

        // ---- S4: gate partials (64 n-tiles x {r@W_ih , h@W_hh}) ----
        {
            int nt = bid & 63, half = bid >> 6;
            const float* A = half ? g_h  : g_actR;
            const float* W = half ? W_hh : W_ih;
            gemm_tile<false>(A, W, 4*HH, nt*64, 0, HH,
                             g_part + (size_t)half*(4*HB), As, Ws, tid, ty, tx);
        }
        grid_barrier(target);

        // ---- S4r: LSTM pointwise ----
        for (int idx = gtid; idx < HB; idx += GRID*NTHR){
            int j = idx >> 6, m = idx & 63;
            size_t o0 = (size_t)j*BB + m;
            size_t st = (size_t)HH*BB;     // 65536: gate stride in n
            float ig = g_part[o0         ] + g_part[4*(size_t)HB + o0         ] + b_ih[j       ] + b_hh[j       ];
            float fg = g_part[o0 +   st  ] + g_part[4*(size_t)HB + o0 +   st  ] + b_ih[j+1024  ] + b_hh[j+1024  ];
            float gg = g_part[o0 + 2*st  ] + g_part[4*(size_t)HB + o0 + 2*st  ] + b_ih[j+2048  ] + b_hh[j+2048  ];
            float og = g_part[o0 + 3*st  ] + g_part[4*(size_t)HB + o0 + 3*st  ] + b_ih[j+3072  ] + b_hh[j+3072  ];
            float cn = sigm(fg)*g_c[idx] + sigm(ig)*tanhf(gg);
            float hn = sigm(og)*tanhf(cn);
            g_c[idx] = cn;
            g_h[idx] = hn;
        }
        grid_barrier(target);

        // ---- S5: d1 partials = relu(h) @ W_o_in ----
        {
            int nt = bid & 15, ks = bid >> 4;
            gemm_tile<true>(g_h, W_o_in, HH, nt*64, ks*128, 128,
                            g_part + (size_t)ks*HB, As, Ws, tid, ty, tx);
        }
        grid_barrier(target);

        // ---- S5r: d1 = relu(sum + b_o_in) -> g_actA ----
        for (int idx = gtid; idx < HB; idx += GRID*NTHR){
            float s = 0.f;
#pragma unroll
            for (int p = 0; p < 8; p++) s += g_part[(size_t)p*HB + idx];
            g_actA[idx] = fmaxf(s + b_o_in[idx >> 6], 0.f);
        }
        grid_barrier(target);

        // ---- S6: d2 partials = d1 @ W_o_h ----
        {
            int nt = bid & 15, ks = bid >> 4;
            gemm_tile<false>(g_actA, W_o_h, HH, nt*64, ks*128, 128,
                             g_part + (size_t)ks*HB, As, Ws, tid, ty, tx);
        }
        grid_barrier(target);

        // ---- S6r: d2 = relu(sum + b_o_h) -> g_actB ----
        for (int idx = gtid; idx < HB; idx += GRID*NTHR){
            float s = 0.f;
#pragma unroll
            for (int p = 0; p < 8; p++) s += g_part[(size_t)p*HB + idx];
            g_actB[idx] = fmaxf(s + b_o_h[idx >> 6], 0.f);
        }
        grid_barrier(target);

        // ---- S7: y partials = d2 @ W_o_out (16 K-splits, N=64) ----
        if (bid < 16)
            gemm_tile<false>(g_actB, W_o_out, OUTD, 0, bid*64, 64,
                             g_part + (size_t)bid*(OUTD*BB), As, Ws, tid, ty, tx);
        grid_barrier(target);

        // ---- S7r: y = sum + b_o_out ; store ys (masked) ; update y buffers --
        for (int idx = gtid; idx < OUTD*BB; idx += GRID*NTHR){
            float s = b_o_out[idx >> 6];
#pragma unroll
            for (int p = 0; p < 16; p++) s += g_part[(size_t)p*(OUTD*BB) + idx];
            int n = idx >> 6, m = idx & 63;
            ys_out[((size_t)m*TTT + t)*OUTD + n] = (t < x_len[m]) ? s : 0.f;
            g_ycur[idx]  = s;   // reference sets y and y_prev both to y_out
            g_yprev[idx] = s;
        }
        grid_barrier(target);
    }
}

// ---------------- launch ----------------------------------------------------
extern "C" void kernel_launch(void* const* d_in, const int* in_sizes, int n_in,
                              void* d_out, int out_size)
{
    (void)in_sizes; (void)n_in; (void)out_size;
    const float* x       = (const float*)d_in[0];
    const int*   x_len   = (const int*)  d_in[1];
    const float* y_0     = (const float*)d_in[2];
    const float* y_1     = (const float*)d_in[3];
    const float* W_e_in  = (const float*)d_in[4];
    const float* b_e_in  = (const float*)d_in[5];
    const float* W_e_h   = (const float*)d_in[6];
    const float* b_e_h   = (const float*)d_in[7];
    const float* W_e_out = (const float*)d_in[8];
    const float* b_e_out = (const float*)d_in[9];
    const float* W_ih    = (const float*)d_in[10];
    const float* W_hh    = (const float*)d_in[11];
    const float* b_ih    = (const float*)d_in[12];
    const float* b_hh    = (const float*)d_in[13];
    const float* W_o_in  = (const float*)d_in[14];
    const float* b_o_in  = (const float*)d_in[15];
    const float* W_o_h   = (const float*)d_in[16];
    const float* b_o_h   = (const float*)d_in[17];
    const float* W_o_out = (const float*)d_in[18];
    const float* b_o_out = (const float*)d_in[19];

    init_kernel<<<64, 256>>>(y_0, y_1);
    rnn_kernel<<<GRID, NTHR>>>(x, x_len,
                               W_e_in, b_e_in, W_e_h, b_e_h, W_e_out, b_e_out,
                               W_ih, W_hh, b_ih, b_hh,
                               W_o_in, b_o_in, W_o_h, b_o_h, W_o_out, b_o_out,
                               (float*)d_out);
}

// round 3
// speedup vs baseline: 1.8044x; 1.8044x over previous
#include <cuda_runtime.h>
#include <math.h>

#define BB    64
#define TTT   512
#define FIN_  256
#define HH    1024
#define OUTD  64
#define GRID  128
#define NTHR  256
#define KSLAB 32
#define HB    (HH*BB)   // 65536

// ---------------- static device scratch ------------------------------------
__device__ __align__(16) float g_xT[(size_t)TTT*FIN_*BB]; // [t][k][m] 32MB
__device__ __align__(16) float g_actA[HB];
__device__ __align__(16) float g_actB[HB];
__device__ __align__(16) float g_actR[HB];
__device__ __align__(16) float g_h[HB];
__device__ __align__(16) float g_hr[HB];
__device__ __align__(16) float g_c[HB];
__device__ __align__(16) float g_part[8*HB];              // 2MB split-K partials
__device__ __align__(16) float g_y2[2*OUTD*BB];           // [y ; y_prev], [j][b]
__device__ unsigned g_bar;

__device__ __forceinline__ float sigm(float v){ return 1.0f/(1.0f + expf(-v)); }

#define CP_ASYNC16(dst, src) \
    asm volatile("cp.async.cg.shared.global [%0], [%1], 16;" :: "r"(dst), "l"(src) : "memory")
#define CP_COMMIT  asm volatile("cp.async.commit_group;" ::: "memory")
#define CP_WAIT(n) asm volatile("cp.async.wait_group %0;" :: "n"(n) : "memory")

// ---------------- grid barrier (elected-thread fences) ----------------------
__device__ __forceinline__ void grid_barrier(unsigned &target){
    __syncthreads();
    if (threadIdx.x == 0){
        __threadfence();                       // cumulative release
        atomicAdd(&g_bar, 1u);
        while (*(volatile unsigned*)&g_bar < target) { }
        __threadfence();                       // acquire + L1 invalidate
    }
    __syncthreads();
    target += GRID;
}

// ---------------- async double-buffered 64x64 tile GEMM ---------------------
// A: k-major, ld 64 (already offset to k0).  W: row-major ldw (already offset
// to (k0, n0)).  outp: partial tile base, layout [n][m], n-stride 64.
// m_eff: rows >= m_eff skip FMA (acc stays 0).
__device__ __noinline__ void gemm_async(
    const float* __restrict__ A, const float* __restrict__ W,
    int ldw, int kc, float* __restrict__ outp, int m_eff,
    float* sA, float* sW, int tid)
{
    const int tx = tid & 15, ty = tid >> 4;
    const int r  = ty;                 // load row 0..15 (and +16)
    const int c4 = tx << 2;            // float offset
    const unsigned la0 = (unsigned)((r*64 + c4) * 4);
    const unsigned la1 = (unsigned)(((r+16)*64 + c4) * 4);
    const unsigned aB = (unsigned)__cvta_generic_to_shared(sA);
    const unsigned wB = (unsigned)__cvta_generic_to_shared(sW);
    const int nslab = kc >> 5;
    const bool live = (ty << 2) < m_eff;

    float acc[4][4] = {{0,0,0,0},{0,0,0,0},{0,0,0,0},{0,0,0,0}};

    // prime slab 0 into buffer 0
    {
        const float* a = A + r*64 + c4;
        const float* w = W + (size_t)r*ldw + c4;
        CP_ASYNC16(aB + la0, a);
        CP_ASYNC16(aB + la1, a + 16*64);
        CP_ASYNC16(wB + la0, w);
        CP_ASYNC16(wB + la1, w + (size_t)16*ldw);
        CP_COMMIT;
    }

    for (int s = 0; s < nslab; s++){
        const unsigned cur = (s & 1) ? (unsigned)(KSLAB*64*4) : 0u;
        if (s + 1 < nslab){
            const unsigned nxt = ((s+1) & 1) ? (unsigned)(KSLAB*64*4) : 0u;
            const float* a = A + (size_t)((s+1)*KSLAB + r)*64 + c4;
            const float* w = W + (size_t)((s+1)*KSLAB + r)*ldw + c4;
            CP_ASYNC16(aB + nxt + la0, a);
            CP_ASYNC16(aB + nxt + la1, a + 16*64);
            CP_ASYNC16(wB + nxt + la0, w);
            CP_ASYNC16(wB + nxt + la1, w + (size_t)16*ldw);
            CP_COMMIT;
            CP_WAIT(1);
        } else {
            CP_WAIT(0);
        }
        __syncthreads();
        if (live){
            const float* As = sA + (cur >> 2);
            const float* Ws = sW + (cur >> 2);
#pragma unroll
            for (int k = 0; k < KSLAB; k++){
                float4 a = *(const float4*)(As + k*64 + (ty << 2));
                float4 w = *(const float4*)(Ws + k*64 + (tx << 2));
                acc[0][0] = fmaf(a.x, w.x, acc[0][0]);
                acc[0][1] = fmaf(a.x, w.y, acc[0][1]);
                acc[0][2] = fmaf(a.x, w.z, acc[0][2]);
                acc[0][3] = fmaf(a.x, w.w, acc[0][3]);
                acc[1][0] = fmaf(a.y, w.x, acc[1][0]);
                acc[1][1] = fmaf(a.y, w.y, acc[1][1]);
                acc[1][2] = fmaf(a.y, w.z, acc[1][2]);
                acc[1][3] = fmaf(a.y, w.w, acc[1][3]);
                acc[2][0] = fmaf(a.z, w.x, acc[2][0]);
                acc[2][1] = fmaf(a.z, w.y, acc[2][1]);
                acc[2][2] = fmaf(a.z, w.z, acc[2][2]);
                acc[2][3] = fmaf(a.z, w.w, acc[2][3]);
                acc[3][0] = fmaf(a.w, w.x, acc[3][0]);
                acc[3][1] = fmaf(a.w, w.y, acc[3][1]);
                acc[3][2] = fmaf(a.w, w.z, acc[3][2]);
                acc[3][3] = fmaf(a.w, w.w, acc[3][3]);
            }
        }
        __syncthreads();
    }

    const int m0 = ty << 2;
#pragma unroll
    for (int j = 0; j < 4; j++){
        *(float4*)(outp + (size_t)((tx << 2) + j)*64 + m0) =
            make_float4(acc[0][j], acc[1][j], acc[2][j], acc[3][j]);
    }
}

// ---------------- init: reset state, transpose x ----------------------------
__global__ void init_kernel(const float* __restrict__ x,
                            const float* __restrict__ y0,
                            const float* __restrict__ y1){
    int i = blockIdx.x * blockDim.x + threadIdx.x;
    int n = gridDim.x * blockDim.x;
    if (i == 0) g_bar = 0u;
    for (int idx = i; idx < HB; idx += n){
        g_h[idx] = 0.f; g_c[idx] = 0.f; g_hr[idx] = 0.f;
    }
    for (int idx = i; idx < OUTD*BB; idx += n){
        int j = idx >> 6, b = idx & 63;
        g_y2[idx]           = y1[b*OUTD + j];
        g_y2[OUTD*BB + idx] = y0[b*OUTD + j];
    }
    // transpose x[m][t][k] -> g_xT[t][k][m]
    const size_t NF4 = (size_t)BB * TTT * (FIN_/4);
    for (size_t f4 = i; f4 < NF4; f4 += n){
        int k4 = (int)(f4 & 63);
        int tt = (int)((f4 >> 6) & 511);
        int m  = (int)(f4 >> 15);
        float4 v = *(const float4*)(x + f4*4);
        size_t base = ((size_t)tt*FIN_ + k4*4)*BB + m;
        g_xT[base       ] = v.x;
        g_xT[base +   BB] = v.y;
        g_xT[base + 2*BB] = v.z;
        g_xT[base + 3*BB] = v.w;
    }
}

// ---------------- persistent RNN kernel -------------------------------------
__global__ void __launch_bounds__(NTHR)
rnn_kernel(const int* __restrict__ x_len,
           const float* __restrict__ W_e_in,  const float* __restrict__ b_e_in,
           const float* __restrict__ W_e_h,   const float* __restrict__ b_e_h,
           const float* __restrict__ W_e_out, const float* __restrict__ b_e_out,
           const float* __restrict__ W_ih,    const float* __restrict__ W_hh,
           const float* __restrict__ b_ih,    const float* __restrict__ b_hh,
           const float* __restrict__ W_o_in,  const float* __restrict__ b_o_in,
           const float* __restrict__ W_o_h,   const float* __restrict__ b_o_h,
           const float* __restrict__ W_o_out, const float* __restrict__ b_o_out,
           float* __restrict__ out)
{
    __shared__ __align__(16) float sA[2*KSLAB*64];   // 16KB
    __shared__ __align__(16) float sW[2*KSLAB*64];   // 16KB
    __shared__ int s_meff[TTT];
    __shared__ int s_xlen[BB];

    const int tid  = threadIdx.x;
    const int bid  = blockIdx.x;
    const int gtid = bid * NTHR + tid;
    unsigned target = GRID;

    float* __restrict__ ys_out   = out;
    float* __restrict__ skip_out = out + (size_t)BB*TTT*OUTD;

    if (tid < BB) s_xlen[tid] = x_len[tid];
    __syncthreads();
    for (int t = tid; t < TTT; t += NTHR){
        int c = 0;
#pragma unroll
        for (int m = 0; m < BB; m++) c += (s_xlen[m] > t) ? 1 : 0;
        s_meff[t] = c;
    }
    __syncthreads();

    for (int t = 0; t < TTT; t++){
        const int me = s_meff[t];

        // ---- S1: e1 partials = [x_t;y;y_prev] @ W_e_in  (16n x 3ks, K=128)
        if (bid < 48){
            int nt = bid & 15, ks = bid >> 4;
            const float* A = (ks < 2) ? (g_xT + ((size_t)t*FIN_ + ks*128)*BB)
                                      : g_y2;
            gemm_async(A, W_e_in + (size_t)(ks*128)*HH + nt*64, HH, 128,
                       g_part + (size_t)ks*HB + (size_t)nt*64*64, me, sA, sW, tid);
        }
        grid_barrier(target);

        // ---- S1r: e1 = relu(sum3 + b_e_in)
        for (int i = gtid*4; i < HB; i += GRID*NTHR*4){
            float4 s0 = *(const float4*)(g_part + i);
            float4 s1 = *(const float4*)(g_part + HB + i);
            float4 s2 = *(const float4*)(g_part + 2*HB + i);
            float bn = b_e_in[i >> 6];
            float4 o;
            o.x = fmaxf(s0.x + s1.x + s2.x + bn, 0.f);
            o.y = fmaxf(s0.y + s1.y + s2.y + bn, 0.f);
            o.z = fmaxf(s0.z + s1.z + s2.z + bn, 0.f);
            o.w = fmaxf(s0.w + s1.w + s2.w + bn, 0.f);
            *(float4*)(g_actA + i) = o;
        }
        grid_barrier(target);

        // ---- S2: e2 partials = e1 @ W_e_h  (16n x 8ks, K=128)
        {
            int nt = bid & 15, ks = bid >> 4;
            gemm_async(g_actA + (size_t)ks*128*BB,
                       W_e_h + (size_t)(ks*128)*HH + nt*64, HH, 128,
                       g_part + (size_t)ks*HB + (size_t)nt*64*64, me, sA, sW, tid);
        }
        grid_barrier(target);

        // ---- S2r: e2 = relu(sum8 + b_e_h)
        for (int i = gtid*4; i < HB; i += GRID*NTHR*4){
            float4 s = *(const float4*)(g_part + i);
#pragma unroll
            for (int p = 1; p < 8; p++){
                float4 v = *(const float4*)(g_part + (size_t)p*HB + i);
                s.x += v.x; s.y += v.y; s.z += v.z; s.w += v.w;
            }
            float bn = b_e_h[i >> 6];
            float4 o;
            o.x = fmaxf(s.x + bn, 0.f); o.y = fmaxf(s.y + bn, 0.f);
            o.z = fmaxf(s.z + bn, 0.f); o.w = fmaxf(s.w + bn, 0.f);
            *(float4*)(g_actB + i) = o;
        }
        grid_barrier(target);

        // ---- S3: e partials = e2 @ W_e_out
        {
            int nt = bid & 15, ks = bid >> 4;
            gemm_async(g_actB + (size_t)ks*128*BB,
                       W_e_out + (size_t)(ks*128)*HH + nt*64, HH, 128,
                       g_part + (size_t)ks*HB + (size_t)nt*64*64, me, sA, sW, tid);
        }
        grid_barrier(target);

        // ---- S3r: e = sum8 + b_e_out; skip store (masked); r = relu(e)
        for (int i = gtid*4; i < HB; i += GRID*NTHR*4){
            float4 s = *(const float4*)(g_part + i);
#pragma unroll
            for (int p = 1; p < 8; p++){
                float4 v = *(const float4*)(g_part + (size_t)p*HB + i);
                s.x += v.x; s.y += v.y; s.z += v.z; s.w += v.w;
            }
            int nn = i >> 6, m0 = i & 63;
            float bn = b_e_out[nn];
            float e0 = s.x + bn, e1 = s.y + bn, e2 = s.z + bn, e3 = s.w + bn;
            skip_out[((size_t)(m0+0)*TTT + t)*HH + nn] = (m0+0 < me) ? e0 : 0.f;
            skip_out[((size_t)(m0+1)*TTT + t)*HH + nn] = (m0+1 < me) ? e1 : 0.f;
            skip_out[((size_t)(m0+2)*TTT + t)*HH + nn] = (m0+2 < me) ? e2 : 0.f;
            skip_out[((size_t)(m0+3)*TTT + t)*HH + nn] = (m0+3 < me) ? e3 : 0.f;
            float4 o = make_float4(fmaxf(e0,0.f), fmaxf(e1,0.f),
                                   fmaxf(e2,0.f), fmaxf(e3,0.f));
            *(float4*)(g_actR + i) = o;
        }
        grid_barrier(target);

        // ---- S4: gate partials (64n x {r@W_ih , h@W_hh}, K=1024)
        {
            int nt = bid & 63, half = bid >> 6;
            const float* Ap = half ? g_h  : g_actR;
            const float* Wp = (half ? W_hh : W_ih) + nt*64;
            gemm_async(Ap, Wp, 4*HH, HH,
                       g_part + (size_t)half*4*HB + (size_t)nt*64*64, me, sA, sW, tid);
        }
        grid_barrier(target);

        // ---- S4r: LSTM pointwise; store h, relu(h)
        for (int idx = gtid; idx < HB; idx += GRID*NTHR){
            int j = idx >> 6, m = idx & 63;
            size_t o0 = (size_t)j*BB + m;
            size_t st = (size_t)HB;
            float ig = g_part[o0       ] + g_part[4*(size_t)HB + o0       ] + b_ih[j     ] + b_hh[j     ];
            float fg = g_part[o0 +   st] + g_part[4*(size_t)HB + o0 +   st] + b_ih[j+1024] + b_hh[j+1024];
            float gg = g_part[o0 + 2*st] + g_part[4*(size_t)HB + o0 + 2*st] + b_ih[j+2048] + b_hh[j+2048];
            float og = g_part[o0 + 3*st] + g_part[4*(size_t)HB + o0 + 3*st] + b_ih[j+3072] + b_hh[j+3072];
            float cn = sigm(fg)*g_c[idx] + sigm(ig)*tanhf(gg);
            float hn = sigm(og)*tanhf(cn);
            g_c[idx]  = cn;
            g_h[idx]  = hn;
            g_hr[idx] = fmaxf(hn, 0.f);
        }
        grid_barrier(target);

        // ---- S5: d1 partials = relu(h) @ W_o_in
        {
            int nt = bid & 15, ks = bid >> 4;
            gemm_async(g_hr + (size_t)ks*128*BB,
                       W_o_in + (size_t)(ks*128)*HH + nt*64, HH, 128,
                       g_part + (size_t)ks*HB + (size_t)nt*64*64, me, sA, sW, tid);
        }
        grid_barrier(target);

        // ---- S5r: d1 = relu(sum8 + b_o_in)
        for (int i = gtid*4; i < HB; i += GRID*NTHR*4){
            float4 s = *(const float4*)(g_part + i);
#pragma unroll
            for (int p = 1; p < 8; p++){
                float4 v = *(const float4*)(g_part + (size_t)p*HB + i);
                s.x += v.x; s.y += v.y; s.z += v.z; s.w += v.w;
            }
            float bn = b_o_in[i >> 6];
            float4 o;
            o.x = fmaxf(s.x + bn, 0.f); o.y = fmaxf(s.y + bn, 0.f);
            o.z = fmaxf(s.z + bn, 0.f); o.w = fmaxf(s.w + bn, 0.f);
            *(float4*)(g_actA + i) = o;
        }
        grid_barrier(target);

        // ---- S6: d2 partials = d1 @ W_o_h
        {
            int nt = bid & 15, ks = bid >> 4;
            gemm_async(g_actA + (size_t)ks*128*BB,
                       W_o_h + (size_t)(ks*128)*HH + nt*64, HH, 128,
                       g_part + (size_t)ks*HB + (size_t)nt*64*64, me, sA, sW, tid);
        }
        grid_barrier(target);

        // ---- S6r: d2 = relu(sum8 + b_o_h)
        for (int i = gtid*4; i < HB; i += GRID*NTHR*4){
            float4 s = *(const float4*)(g_part + i);
#pragma unroll
            for (int p = 1; p < 8; p++){
                float4 v = *(const float4*)(g_part + (size_t)p*HB + i);
                s.x += v.x; s.y += v.y; s.z += v.z; s.w += v.w;
            }
            float bn = b_o_h[i >> 6];
            float4 o;
            o.x = fmaxf(s.x + bn, 0.f); o.y = fmaxf(s.y + bn, 0.f);
            o.z = fmaxf(s.z + bn, 0.f); o.w = fmaxf(s.w + bn, 0.f);
            *(float4*)(g_actB + i) = o;
        }
        grid_barrier(target);

        // ---- S7: y partials = d2 @ W_o_out  (16 ks, K=64 each)
        if (bid < 16){
            gemm_async(g_actB + (size_t)bid*64*BB,
                       W_o_out + (size_t)bid*64*64, OUTD, 64,
                       g_part + (size_t)bid*4096, me, sA, sW, tid);
        }
        grid_barrier(target);

        // ---- S7r: y = sum16 + b_o_out; store ys (masked); update y buffers
        for (int idx = gtid; idx < OUTD*BB; idx += GRID*NTHR){
            float s = b_o_out[idx >> 6];
#pragma unroll
            for (int p = 0; p < 16; p++) s += g_part[(size_t)p*4096 + idx];
            int nn = idx >> 6, m = idx & 63;
            ys_out[((size_t)m*TTT + t)*OUTD + nn] = (m < me) ? s : 0.f;
            g_y2[idx]           = s;
            g_y2[OUTD*BB + idx] = s;
        }
        grid_barrier(target);
    }
}

// ---------------- launch -----------------------------------------------------
extern "C" void kernel_launch(void* const* d_in, const int* in_sizes, int n_in,
                              void* d_out, int out_size)
{
    (void)in_sizes; (void)n_in; (void)out_size;
    const float* x       = (const float*)d_in[0];
    const int*   x_len   = (const int*)  d_in[1];
    const float* y_0     = (const float*)d_in[2];
    const float* y_1     = (const float*)d_in[3];
    const float* W_e_in  = (const float*)d_in[4];
    const float* b_e_in  = (const float*)d_in[5];
    const float* W_e_h   = (const float*)d_in[6];
    const float* b_e_h   = (const float*)d_in[7];
    const float* W_e_out = (const float*)d_in[8];
    const float* b_e_out = (const float*)d_in[9];
    const float* W_ih    = (const float*)d_in[10];
    const float* W_hh    = (const float*)d_in[11];
    const float* b_ih    = (const float*)d_in[12];
    const float* b_hh    = (const float*)d_in[13];
    const float* W_o_in  = (const float*)d_in[14];
    const float* b_o_in  = (const float*)d_in[15];
    const float* W_o_h   = (const float*)d_in[16];
    const float* b_o_h   = (const float*)d_in[17];
    const float* W_o_out = (const float*)d_in[18];
    const float* b_o_out = (const float*)d_in[19];

    init_kernel<<<512, 256>>>(x, y_0, y_1);
    rnn_kernel<<<GRID, NTHR>>>(x_len,
                               W_e_in, b_e_in, W_e_h, b_e_h, W_e_out, b_e_out,
                               W_ih, W_hh, b_ih, b_hh,
                               W_o_in, b_o_in, W_o_h, b_o_h, W_o_out, b_o_out,
                               (float*)d_out);
}

// round 4
// speedup vs baseline: 1.9751x; 1.0946x over previous
#include <cuda_runtime.h>
#include <math.h>

#define BB    64
#define TTT   512
#define FIN_  256
#define HH    1024
#define OUTD  64
#define GRID  256
#define NTHR  256
#define KSLAB 32
#define HB    (HH*BB)   // 65536

// ---------------- static device scratch ------------------------------------
__device__ __align__(16) float g_xT[(size_t)TTT*FIN_*BB]; // [t][k][m] 32MB
__device__ __align__(16) float g_Wcat[2048*4096];         // [W_ih;W_hh] 32MB
__device__ __align__(16) float g_actA[HB];
__device__ __align__(16) float g_actB[HB];
__device__ __align__(16) float g_rh[2*HB];   // rows 0-1023: r=relu(e); 1024-2047: h
__device__ __align__(16) float g_hr[HB];     // relu(h)
__device__ __align__(16) float g_c[HB];
__device__ __align__(16) float g_part[16*HB];             // 4MB split-K partials
__device__ __align__(16) float g_y2[2*OUTD*BB];           // [y ; y_prev], [j][b]
__device__ unsigned g_bar;

__device__ __forceinline__ float sigm(float v){ return 1.0f/(1.0f + expf(-v)); }

#define CP_ASYNC16(dst, src) \
    asm volatile("cp.async.cg.shared.global [%0], [%1], 16;" :: "r"(dst), "l"(src) : "memory")
#define CP_COMMIT  asm volatile("cp.async.commit_group;" ::: "memory")
#define CP_WAIT(n) asm volatile("cp.async.wait_group %0;" :: "n"(n) : "memory")

// ---------------- grid barrier (elected-thread fences) ----------------------
__device__ __forceinline__ void grid_barrier(unsigned &target){
    __syncthreads();
    if (threadIdx.x == 0){
        __threadfence();                       // cumulative release
        atomicAdd(&g_bar, 1u);
        while (*(volatile unsigned*)&g_bar < target) { }
        __threadfence();                       // acquire
    }
    __syncthreads();
    target += GRID;
}

// ---------------- async double-buffered 64x64 tile GEMM ---------------------
// A: k-major, ld 64 (pre-offset to k0). W: row-major ldw (pre-offset to k0,n0).
// outp: partial tile [n][m], n-stride 64. Rows >= m_eff skip FMA.
__device__ __noinline__ void gemm_async(
    const float* __restrict__ A, const float* __restrict__ W,
    int ldw, int kc, float* __restrict__ outp, int m_eff,
    float* sA, float* sW, int tid)
{
    const int tx = tid & 15, ty = tid >> 4;
    const int r  = ty;
    const int c4 = tx << 2;
    const unsigned la0 = (unsigned)((r*64 + c4) * 4);
    const unsigned la1 = (unsigned)(((r+16)*64 + c4) * 4);
    const unsigned aB = (unsigned)__cvta_generic_to_shared(sA);
    const unsigned wB = (unsigned)__cvta_generic_to_shared(sW);
    const int nslab = kc >> 5;
    const bool live = (ty << 2) < m_eff;

    float acc[4][4] = {{0,0,0,0},{0,0,0,0},{0,0,0,0},{0,0,0,0}};

    {
        const float* a = A + r*64 + c4;
        const float* w = W + (size_t)r*ldw + c4;
        CP_ASYNC16(aB + la0, a);
        CP_ASYNC16(aB + la1, a + 16*64);
        CP_ASYNC16(wB + la0, w);
        CP_ASYNC16(wB + la1, w + (size_t)16*ldw);
        CP_COMMIT;
    }

    for (int s = 0; s < nslab; s++){
        const unsigned cur = (s & 1) ? (unsigned)(KSLAB*64*4) : 0u;
        if (s + 1 < nslab){
            const unsigned nxt = ((s+1) & 1) ? (unsigned)(KSLAB*64*4) : 0u;
            const float* a = A + (size_t)((s+1)*KSLAB + r)*64 + c4;
            const float* w = W + (size_t)((s+1)*KSLAB + r)*ldw + c4;
            CP_ASYNC16(aB + nxt + la0, a);
            CP_ASYNC16(aB + nxt + la1, a + 16*64);
            CP_ASYNC16(wB + nxt + la0, w);
            CP_ASYNC16(wB + nxt + la1, w + (size_t)16*ldw);
            CP_COMMIT;
            CP_WAIT(1);
        } else {
            CP_WAIT(0);
        }
        __syncthreads();
        if (live){
            const float* As = sA + (cur >> 2);
            const float* Ws = sW + (cur >> 2);
#pragma unroll
            for (int k = 0; k < KSLAB; k++){
                float4 a = *(const float4*)(As + k*64 + (ty << 2));
                float4 w = *(const float4*)(Ws + k*64 + (tx << 2));
                acc[0][0] = fmaf(a.x, w.x, acc[0][0]);
                acc[0][1] = fmaf(a.x, w.y, acc[0][1]);
                acc[0][2] = fmaf(a.x, w.z, acc[0][2]);
                acc[0][3] = fmaf(a.x, w.w, acc[0][3]);
                acc[1][0] = fmaf(a.y, w.x, acc[1][0]);
                acc[1][1] = fmaf(a.y, w.y, acc[1][1]);
                acc[1][2] = fmaf(a.y, w.z, acc[1][2]);
                acc[1][3] = fmaf(a.y, w.w, acc[1][3]);
                acc[2][0] = fmaf(a.z, w.x, acc[2][0]);
                acc[2][1] = fmaf(a.z, w.y, acc[2][1]);
                acc[2][2] = fmaf(a.z, w.z, acc[2][2]);
                acc[2][3] = fmaf(a.z, w.w, acc[2][3]);
                acc[3][0] = fmaf(a.w, w.x, acc[3][0]);
                acc[3][1] = fmaf(a.w, w.y, acc[3][1]);
                acc[3][2] = fmaf(a.w, w.z, acc[3][2]);
                acc[3][3] = fmaf(a.w, w.w, acc[3][3]);
            }
        }
        __syncthreads();
    }

    const int m0 = ty << 2;
#pragma unroll
    for (int j = 0; j < 4; j++){
        *(float4*)(outp + (size_t)((tx << 2) + j)*64 + m0) =
            make_float4(acc[0][j], acc[1][j], acc[2][j], acc[3][j]);
    }
}

// ---------------- init: reset state, transpose x, pack W_cat ----------------
__global__ void init_kernel(const float* __restrict__ x,
                            const float* __restrict__ y0,
                            const float* __restrict__ y1,
                            const float* __restrict__ W_ih,
                            const float* __restrict__ W_hh){
    int i = blockIdx.x * blockDim.x + threadIdx.x;
    int n = gridDim.x * blockDim.x;
    if (i == 0) g_bar = 0u;
    for (int idx = i; idx < 2*HB; idx += n) g_rh[idx] = 0.f;
    for (int idx = i; idx < HB; idx += n){ g_c[idx] = 0.f; g_hr[idx] = 0.f; }
    for (int idx = i; idx < OUTD*BB; idx += n){
        int j = idx >> 6, b = idx & 63;
        g_y2[idx]           = y1[b*OUTD + j];
        g_y2[OUTD*BB + idx] = y0[b*OUTD + j];
    }
    // pack [W_ih ; W_hh] -> g_Wcat (row-major 2048 x 4096)
    const int NW4 = 1024*1024;   // 4096*1024/4
    for (int f4 = i; f4 < NW4; f4 += n){
        *(float4*)(g_Wcat + (size_t)f4*4)              = *(const float4*)(W_ih + (size_t)f4*4);
        *(float4*)(g_Wcat + (size_t)1024*4096 + (size_t)f4*4) = *(const float4*)(W_hh + (size_t)f4*4);
    }
    // transpose x[m][t][k] -> g_xT[t][k][m]
    const size_t NF4 = (size_t)BB * TTT * (FIN_/4);
    for (size_t f4 = i; f4 < NF4; f4 += n){
        int k4 = (int)(f4 & 63);
        int tt = (int)((f4 >> 6) & 511);
        int m  = (int)(f4 >> 15);
        float4 v = *(const float4*)(x + f4*4);
        size_t base = ((size_t)tt*FIN_ + k4*4)*BB + m;
        g_xT[base       ] = v.x;
        g_xT[base +   BB] = v.y;
        g_xT[base + 2*BB] = v.z;
        g_xT[base + 3*BB] = v.w;
    }
}

// ---------------- persistent RNN kernel -------------------------------------
__global__ void __launch_bounds__(NTHR)
rnn_kernel(const int* __restrict__ x_len,
           const float* __restrict__ W_e_in,  const float* __restrict__ b_e_in,
           const float* __restrict__ W_e_h,   const float* __restrict__ b_e_h,
           const float* __restrict__ W_e_out, const float* __restrict__ b_e_out,
           const float* __restrict__ b_ih,    const float* __restrict__ b_hh,
           const float* __restrict__ W_o_in,  const float* __restrict__ b_o_in,
           const float* __restrict__ W_o_h,   const float* __restrict__ b_o_h,
           const float* __restrict__ W_o_out, const float* __restrict__ b_o_out,
           float* __restrict__ out)
{
    __shared__ __align__(16) float sA[2*KSLAB*64];   // 16KB
    __shared__ __align__(16) float sW[2*KSLAB*64];   // 16KB
    __shared__ int s_meff[TTT];
    __shared__ int s_xlen[BB];

    const int tid  = threadIdx.x;
    const int bid  = blockIdx.x;
    const int gtid = bid * NTHR + tid;
    unsigned target = GRID;

    float* __restrict__ ys_out   = out;
    float* __restrict__ skip_out = out + (size_t)BB*TTT*OUTD;

    if (tid < BB) s_xlen[tid] = x_len[tid];
    __syncthreads();
    for (int t = tid; t < TTT; t += NTHR){
        int c = 0;
#pragma unroll
        for (int m = 0; m < BB; m++) c += (s_xlen[m] > t) ? 1 : 0;
        s_meff[t] = c;
    }
    __syncthreads();

    for (int t = 0; t < TTT; t++){
        const int me = s_meff[t];

        // ---- S1: e1 partials = [x_t;y;y_prev] @ W_e_in  (16nt x 6ks, kc=64)
        if (bid < 96){
            int nt = bid & 15, ks = bid >> 4;
            const float* A = (ks < 4) ? (g_xT + ((size_t)t*FIN_ + ks*64)*BB)
                                      : (g_y2 + (size_t)(ks-4)*64*BB);
            gemm_async(A, W_e_in + (size_t)(ks*64)*HH + nt*64, HH, 64,
                       g_part + (size_t)ks*HB + (size_t)nt*4096, me, sA, sW, tid);
        }
        grid_barrier(target);

        // ---- S1r: e1 = relu(sum6 + b_e_in)
        for (int idx = gtid; idx < HB; idx += GRID*NTHR){
            float s = b_e_in[idx >> 6];
#pragma unroll
            for (int p = 0; p < 6; p++) s += g_part[(size_t)p*HB + idx];
            g_actA[idx] = fmaxf(s, 0.f);
        }
        grid_barrier(target);

        // ---- S2: e2 partials = e1 @ W_e_h  (16nt x 16ks, kc=64)
        {
            int nt = bid & 15, ks = bid >> 4;
            gemm_async(g_actA + (size_t)ks*64*BB,
                       W_e_h + (size_t)(ks*64)*HH + nt*64, HH, 64,
                       g_part + (size_t)ks*HB + (size_t)nt*4096, me, sA, sW, tid);
        }
        grid_barrier(target);

        // ---- S2r: e2 = relu(sum16 + b_e_h)
        for (int idx = gtid; idx < HB; idx += GRID*NTHR){
            float s = b_e_h[idx >> 6];
#pragma unroll
            for (int p = 0; p < 16; p++) s += g_part[(size_t)p*HB + idx];
            g_actB[idx] = fmaxf(s, 0.f);
        }
        grid_barrier(target);

        // ---- S3: e partials = e2 @ W_e_out
        {
            int nt = bid & 15, ks = bid >> 4;
            gemm_async(g_actB + (size_t)ks*64*BB,
                       W_e_out + (size_t)(ks*64)*HH + nt*64, HH, 64,
                       g_part + (size_t)ks*HB + (size_t)nt*4096, me, sA, sW, tid);
        }
        grid_barrier(target);

        // ---- S3r: e = sum16 + b_e_out; skip store (masked); r -> g_rh[0:HB]
        for (int idx = gtid; idx < HB; idx += GRID*NTHR){
            float s = b_e_out[idx >> 6];
#pragma unroll
            for (int p = 0; p < 16; p++) s += g_part[(size_t)p*HB + idx];
            int nn = idx >> 6, m = idx & 63;
            skip_out[((size_t)m*TTT + t)*HH + nn] = (m < me) ? s : 0.f;
            g_rh[idx] = fmaxf(s, 0.f);
        }
        grid_barrier(target);

        // ---- S4: gate partials = [r;h] @ W_cat  (64nt x 4ks, kc=512)
        {
            int nt = bid & 63, ks = bid >> 6;
            gemm_async(g_rh + (size_t)ks*512*BB,
                       g_Wcat + (size_t)(ks*512)*4096 + nt*64, 4096, 512,
                       g_part + (size_t)ks*(4*HB) + (size_t)nt*4096, me, sA, sW, tid);
        }
        grid_barrier(target);

        // ---- S4r: LSTM pointwise; h -> g_rh[HB:], relu(h) -> g_hr
        for (int idx = gtid; idx < HB; idx += GRID*NTHR){
            int j = idx >> 6, m = idx & 63;
            size_t o0 = (size_t)j*BB + m;
            float ig = b_ih[j     ] + b_hh[j     ];
            float fg = b_ih[j+1024] + b_hh[j+1024];
            float gg = b_ih[j+2048] + b_hh[j+2048];
            float og = b_ih[j+3072] + b_hh[j+3072];
#pragma unroll
            for (int p = 0; p < 4; p++){
                const float* gp = g_part + (size_t)p*(4*HB);
                ig += gp[o0           ];
                fg += gp[o0 +     HB  ];
                gg += gp[o0 + 2*(size_t)HB];
                og += gp[o0 + 3*(size_t)HB];
            }
            float cn = sigm(fg)*g_c[idx] + sigm(ig)*tanhf(gg);
            float hn = sigm(og)*tanhf(cn);
            g_c[idx]       = cn;
            g_rh[HB + idx] = hn;
            g_hr[idx]      = fmaxf(hn, 0.f);
        }
        grid_barrier(target);

        // ---- S5: d1 partials = relu(h) @ W_o_in
        {
            int nt = bid & 15, ks = bid >> 4;
            gemm_async(g_hr + (size_t)ks*64*BB,
                       W_o_in + (size_t)(ks*64)*HH + nt*64, HH, 64,
                       g_part + (size_t)ks*HB + (size_t)nt*4096, me, sA, sW, tid);
        }
        grid_barrier(target);

        // ---- S5r: d1 = relu(sum16 + b_o_in)
        for (int idx = gtid; idx < HB; idx += GRID*NTHR){
            float s = b_o_in[idx >> 6];
#pragma unroll
            for (int p = 0; p < 16; p++) s += g_part[(size_t)p*HB + idx];
            g_actA[idx] = fmaxf(s, 0.f);
        }
        grid_barrier(target);

        // ---- S6: d2 partials = d1 @ W_o_h
        {
            int nt = bid & 15, ks = bid >> 4;
            gemm_async(g_actA + (size_t)ks*64*BB,
                       W_o_h + (size_t)(ks*64)*HH + nt*64, HH, 64,
                       g_part + (size_t)ks*HB + (size_t)nt*4096, me, sA, sW, tid);
        }
        grid_barrier(target);

        // ---- S6r: d2 = relu(sum16 + b_o_h)
        for (int idx = gtid; idx < HB; idx += GRID*NTHR){
            float s = b_o_h[idx >> 6];
#pragma unroll
            for (int p = 0; p < 16; p++) s += g_part[(size_t)p*HB + idx];
            g_actB[idx] = fmaxf(s, 0.f);
        }
        grid_barrier(target);

        // ---- S7: y partials = d2 @ W_o_out  (16 ks, kc=64)
        if (bid < 16){
            gemm_async(g_actB + (size_t)bid*64*BB,
                       W_o_out + (size_t)bid*64*64, OUTD, 64,
                       g_part + (size_t)bid*4096, me, sA, sW, tid);
        }
        grid_barrier(target);

        // ---- S7r: y = sum16 + b_o_out; store ys (masked); update y buffers
        for (int idx = gtid; idx < OUTD*BB; idx += GRID*NTHR){
            float s = b_o_out[idx >> 6];
#pragma unroll
            for (int p = 0; p < 16; p++) s += g_part[(size_t)p*4096 + idx];
            int nn = idx >> 6, m = idx & 63;
            ys_out[((size_t)m*TTT + t)*OUTD + nn] = (m < me) ? s : 0.f;
            g_y2[idx]           = s;
            g_y2[OUTD*BB + idx] = s;
        }
        grid_barrier(target);
    }
}

// ---------------- launch -----------------------------------------------------
extern "C" void kernel_launch(void* const* d_in, const int* in_sizes, int n_in,
                              void* d_out, int out_size)
{
    (void)in_sizes; (void)n_in; (void)out_size;
    const float* x       = (const float*)d_in[0];
    const int*   x_len   = (const int*)  d_in[1];
    const float* y_0     = (const float*)d_in[2];
    const float* y_1     = (const float*)d_in[3];
    const float* W_e_in  = (const float*)d_in[4];
    const float* b_e_in  = (const float*)d_in[5];
    const float* W_e_h   = (const float*)d_in[6];
    const float* b_e_h   = (const float*)d_in[7];
    const float* W_e_out = (const float*)d_in[8];
    const float* b_e_out = (const float*)d_in[9];
    const float* W_ih    = (const float*)d_in[10];
    const float* W_hh    = (const float*)d_in[11];
    const float* b_ih    = (const float*)d_in[12];
    const float* b_hh    = (const float*)d_in[13];
    const float* W_o_in  = (const float*)d_in[14];
    const float* b_o_in  = (const float*)d_in[15];
    const float* W_o_h   = (const float*)d_in[16];
    const float* b_o_h   = (const float*)d_in[17];
    const float* W_o_out = (const float*)d_in[18];
    const float* b_o_out = (const float*)d_in[19];

    init_kernel<<<512, 256>>>(x, y_0, y_1, W_ih, W_hh);
    rnn_kernel<<<GRID, NTHR>>>(x_len,
                               W_e_in, b_e_in, W_e_h, b_e_h, W_e_out, b_e_out,
                               b_ih, b_hh,
                               W_o_in, b_o_in, W_o_h, b_o_h, W_o_out, b_o_out,
                               (float*)d_out);
}

// round 5
// speedup vs baseline: 2.5837x; 1.3081x over previous
#include <cuda_runtime.h>
#include <math.h>
#include <stdint.h>

#define BB    64
#define TTT   512
#define FIN_  256
#define HH    1024
#define OUTD  64
#define GRID  256
#define NTHR  256
#define KSLAB 32
#define SST   72            // smem row stride in floats (72 mod 32 == 8 -> conflict-free frags)
#define HB    (HH*BB)       // 65536

// ---------------- static device scratch ------------------------------------
__device__ __align__(16) float g_xT[(size_t)TTT*FIN_*BB]; // [t][k][m] 32MB (tf32-rounded)
__device__ __align__(16) float g_Wcat[2048*4096];         // [W_ih;W_hh] rounded
__device__ __align__(16) float g_We_in[384*HH];
__device__ __align__(16) float g_We_h[HH*HH];
__device__ __align__(16) float g_We_out[HH*HH];
__device__ __align__(16) float g_Wo_in[HH*HH];
__device__ __align__(16) float g_Wo_h[HH*HH];
__device__ __align__(16) float g_Wo_out[HH*OUTD];
__device__ __align__(16) float g_actA[HB];
__device__ __align__(16) float g_actB[HB];
__device__ __align__(16) float g_rh[2*HB];   // rows 0-1023: r=relu(e); 1024-2047: h  (rounded)
__device__ __align__(16) float g_hr[HB];     // relu(h) rounded
__device__ __align__(16) float g_c[HB];      // exact fp32 state
__device__ __align__(16) float g_part[16*HB];             // 4MB split-K partials
__device__ __align__(16) float g_y2[2*OUTD*BB];           // [y ; y_prev], [j][b]  rounded
__device__ unsigned g_bar;

__device__ __forceinline__ float sigm(float v){ return 1.0f/(1.0f + expf(-v)); }

__device__ __forceinline__ float tf32r(float v){
    uint32_t u; asm("cvt.rna.tf32.f32 %0, %1;" : "=r"(u) : "f"(v));
    return __uint_as_float(u);
}

#define CP_ASYNC16(dst, src) \
    asm volatile("cp.async.cg.shared.global [%0], [%1], 16;" :: "r"(dst), "l"(src) : "memory")
#define CP_COMMIT  asm volatile("cp.async.commit_group;" ::: "memory")
#define CP_WAIT(n) asm volatile("cp.async.wait_group %0;" :: "n"(n) : "memory")

__device__ __forceinline__ void mma_tf32(float c[4], const uint32_t a[4], const uint32_t b[2]){
    asm volatile("mma.sync.aligned.m16n8k8.row.col.f32.tf32.tf32.f32 "
        "{%0,%1,%2,%3}, {%4,%5,%6,%7}, {%8,%9}, {%0,%1,%2,%3};"
        : "+f"(c[0]), "+f"(c[1]), "+f"(c[2]), "+f"(c[3])
        : "r"(a[0]), "r"(a[1]), "r"(a[2]), "r"(a[3]), "r"(b[0]), "r"(b[1]));
}

// ---------------- grid barrier ----------------------------------------------
__device__ __forceinline__ void grid_barrier(unsigned &target){
    __syncthreads();
    if (threadIdx.x == 0){
        __threadfence();
        atomicAdd(&g_bar, 1u);
        while (*(volatile unsigned*)&g_bar < target) { }
        __threadfence();
    }
    __syncthreads();
    target += GRID;
}

// ---------------- 64x64 tile GEMM via tf32 mma.sync --------------------------
// A: k-major, ld 64 (pre-offset to k0). W: row-major ldw (pre-offset to k0,n0).
// outp: partial tile [n][m], n-stride 64. m-tiles starting >= m_eff skipped.
__device__ __noinline__ void gemm_mma(
    const float* __restrict__ A, const float* __restrict__ W,
    int ldw, int kc, float* __restrict__ outp, int m_eff,
    float* sA, float* sW, int tid)
{
    const int lane = tid & 31;
    const int wid  = tid >> 5;
    const int wm = wid & 1;        // m half   (32 rows)
    const int wn = wid >> 1;       // n quarter(16 cols)
    const int fr = lane >> 2;      // 0..7
    const int fc = lane & 3;       // 0..3

    const int r  = tid >> 4;       // staging row 0..15 (+16)
    const int c4 = (tid & 15) << 2;
    const unsigned la0 = (unsigned)((r*SST + c4) * 4);
    const unsigned la1 = (unsigned)(((r+16)*SST + c4) * 4);
    const unsigned aB = (unsigned)__cvta_generic_to_shared(sA);
    const unsigned wB = (unsigned)__cvta_generic_to_shared(sW);
    const int nslab = kc >> 5;

    const bool live0 = (wm*32)      < m_eff;
    const bool live1 = (wm*32 + 16) < m_eff;

    float acc[2][2][4];
#pragma unroll
    for (int i = 0; i < 2; i++)
#pragma unroll
        for (int j = 0; j < 2; j++)
#pragma unroll
            for (int q = 0; q < 4; q++) acc[i][j][q] = 0.f;

    // prime slab 0
    {
        const float* a = A + r*64 + c4;
        const float* w = W + (size_t)r*ldw + c4;
        CP_ASYNC16(aB + la0, a);
        CP_ASYNC16(aB + la1, a + 16*64);
        CP_ASYNC16(wB + la0, w);
        CP_ASYNC16(wB + la1, w + (size_t)16*ldw);
        CP_COMMIT;
    }

    for (int s = 0; s < nslab; s++){
        const int cur = (s & 1) ? KSLAB*SST : 0;
        if (s + 1 < nslab){
            const unsigned nxt = ((s+1) & 1) ? (unsigned)(KSLAB*SST*4) : 0u;
            const float* a = A + (size_t)((s+1)*KSLAB + r)*64 + c4;
            const float* w = W + (size_t)((s+1)*KSLAB + r)*ldw + c4;
            CP_ASYNC16(aB + nxt + la0, a);
            CP_ASYNC16(aB + nxt + la1, a + 16*64);
            CP_ASYNC16(wB + nxt + la0, w);
            CP_ASYNC16(wB + nxt + la1, w + (size_t)16*ldw);
            CP_COMMIT;
            CP_WAIT(1);
        } else {
            CP_WAIT(0);
        }
        __syncthreads();

        const float* As = sA + cur;
        const float* Ws = sW + cur;
#pragma unroll
        for (int kq = 0; kq < KSLAB/8; kq++){
            const float* Ak = As + kq*8*SST;
            const float* Wk = Ws + kq*8*SST;
            uint32_t af[2][4], bf[2][2];
#pragma unroll
            for (int mt = 0; mt < 2; mt++){
                const int m0 = wm*32 + mt*16;
                af[mt][0] = __float_as_uint(Ak[ fc   *SST + m0 + fr    ]);
                af[mt][1] = __float_as_uint(Ak[ fc   *SST + m0 + fr + 8]);
                af[mt][2] = __float_as_uint(Ak[(fc+4)*SST + m0 + fr    ]);
                af[mt][3] = __float_as_uint(Ak[(fc+4)*SST + m0 + fr + 8]);
            }
#pragma unroll
            for (int nq = 0; nq < 2; nq++){
                const int n0 = wn*16 + nq*8;
                bf[nq][0] = __float_as_uint(Wk[ fc   *SST + n0 + fr]);
                bf[nq][1] = __float_as_uint(Wk[(fc+4)*SST + n0 + fr]);
            }
            if (live0){ mma_tf32(acc[0][0], af[0], bf[0]);
                        mma_tf32(acc[0][1], af[0], bf[1]); }
            if (live1){ mma_tf32(acc[1][0], af[1], bf[0]);
                        mma_tf32(acc[1][1], af[1], bf[1]); }
        }
        __syncthreads();
    }

#pragma unroll
    for (int mt = 0; mt < 2; mt++){
        const int m0 = wm*32 + mt*16;
#pragma unroll
        for (int nq = 0; nq < 2; nq++){
            const int n0  = wn*16 + nq*8;
            const int col = n0 + 2*fc;
            outp[(size_t)col*64     + m0 + fr    ] = acc[mt][nq][0];
            outp[(size_t)(col+1)*64 + m0 + fr    ] = acc[mt][nq][1];
            outp[(size_t)col*64     + m0 + fr + 8] = acc[mt][nq][2];
            outp[(size_t)(col+1)*64 + m0 + fr + 8] = acc[mt][nq][3];
        }
    }
}

// ---------------- init: round weights to tf32, transpose x, reset state -----
__global__ void init_kernel(const float* __restrict__ x,
                            const float* __restrict__ y0,
                            const float* __restrict__ y1,
                            const float* __restrict__ W_e_in,
                            const float* __restrict__ W_e_h,
                            const float* __restrict__ W_e_out,
                            const float* __restrict__ W_ih,
                            const float* __restrict__ W_hh,
                            const float* __restrict__ W_o_in,
                            const float* __restrict__ W_o_h,
                            const float* __restrict__ W_o_out){
    int i = blockIdx.x * blockDim.x + threadIdx.x;
    int n = gridDim.x * blockDim.x;
    if (i == 0) g_bar = 0u;
    for (int idx = i; idx < 2*HB; idx += n) g_rh[idx] = 0.f;
    for (int idx = i; idx < HB; idx += n){ g_c[idx] = 0.f; g_hr[idx] = 0.f; }
    for (int idx = i; idx < OUTD*BB; idx += n){
        int j = idx >> 6, b = idx & 63;
        g_y2[idx]           = tf32r(y1[b*OUTD + j]);
        g_y2[OUTD*BB + idx] = tf32r(y0[b*OUTD + j]);
    }
    // rounded weight copies
    for (int idx = i; idx < 384*HH;  idx += n) g_We_in[idx]  = tf32r(W_e_in[idx]);
    for (int idx = i; idx < HH*HH;   idx += n) g_We_h[idx]   = tf32r(W_e_h[idx]);
    for (int idx = i; idx < HH*HH;   idx += n) g_We_out[idx] = tf32r(W_e_out[idx]);
    for (int idx = i; idx < HH*HH;   idx += n) g_Wo_in[idx]  = tf32r(W_o_in[idx]);
    for (int idx = i; idx < HH*HH;   idx += n) g_Wo_h[idx]   = tf32r(W_o_h[idx]);
    for (int idx = i; idx < HH*OUTD; idx += n) g_Wo_out[idx] = tf32r(W_o_out[idx]);
    // pack [W_ih ; W_hh] -> g_Wcat (row-major 2048 x 4096), rounded
    const int NW = 4096*1024;
    for (int f = i; f < NW; f += n){
        g_Wcat[f]                     = tf32r(W_ih[f]);
        g_Wcat[(size_t)1024*4096 + f] = tf32r(W_hh[f]);
    }
    // transpose x[m][t][k] -> g_xT[t][k][m], rounded
    const size_t NF4 = (size_t)BB * TTT * (FIN_/4);
    for (size_t f4 = i; f4 < NF4; f4 += n){
        int k4 = (int)(f4 & 63);
        int tt = (int)((f4 >> 6) & 511);
        int m  = (int)(f4 >> 15);
        float4 v = *(const float4*)(x + f4*4);
        size_t base = ((size_t)tt*FIN_ + k4*4)*BB + m;
        g_xT[base       ] = tf32r(v.x);
        g_xT[base +   BB] = tf32r(v.y);
        g_xT[base + 2*BB] = tf32r(v.z);
        g_xT[base + 3*BB] = tf32r(v.w);
    }
}

// ---------------- persistent RNN kernel -------------------------------------
__global__ void __launch_bounds__(NTHR)
rnn_kernel(const int* __restrict__ x_len,
           const float* __restrict__ b_e_in,  const float* __restrict__ b_e_h,
           const float* __restrict__ b_e_out,
           const float* __restrict__ b_ih,    const float* __restrict__ b_hh,
           const float* __restrict__ b_o_in,  const float* __restrict__ b_o_h,
           const float* __restrict__ b_o_out,
           float* __restrict__ out)
{
    __shared__ __align__(16) float sA[2*KSLAB*SST];   // 18KB
    __shared__ __align__(16) float sW[2*KSLAB*SST];   // 18KB
    __shared__ int s_meff[TTT];
    __shared__ int s_xlen[BB];

    const int tid  = threadIdx.x;
    const int bid  = blockIdx.x;
    const int gtid = bid * NTHR + tid;
    unsigned target = GRID;

    float* __restrict__ ys_out   = out;
    float* __restrict__ skip_out = out + (size_t)BB*TTT*OUTD;

    if (tid < BB) s_xlen[tid] = x_len[tid];
    __syncthreads();
    for (int t = tid; t < TTT; t += NTHR){
        int c = 0;
#pragma unroll
        for (int m = 0; m < BB; m++) c += (s_xlen[m] > t) ? 1 : 0;
        s_meff[t] = c;
    }
    __syncthreads();

    for (int t = 0; t < TTT; t++){
        const int me = s_meff[t];

        // ---- S1: e1 partials = [x_t;y;y_prev] @ W_e_in  (16nt x 6ks, kc=64)
        if (bid < 96){
            int nt = bid & 15, ks = bid >> 4;
            const float* A = (ks < 4) ? (g_xT + ((size_t)t*FIN_ + ks*64)*BB)
                                      : (g_y2 + (size_t)(ks-4)*64*BB);
            gemm_mma(A, g_We_in + (size_t)(ks*64)*HH + nt*64, HH, 64,
                     g_part + (size_t)ks*HB + (size_t)nt*4096, me, sA, sW, tid);
        }
        grid_barrier(target);

        // ---- S1r: e1 = relu(sum6 + b_e_in)  [tf32-rounded]
        for (int idx = gtid; idx < HB; idx += GRID*NTHR){
            float s = b_e_in[idx >> 6];
#pragma unroll
            for (int p = 0; p < 6; p++) s += g_part[(size_t)p*HB + idx];
            g_actA[idx] = tf32r(fmaxf(s, 0.f));
        }
        grid_barrier(target);

        // ---- S2: e2 partials = e1 @ W_e_h  (16nt x 16ks, kc=64)
        {
            int nt = bid & 15, ks = bid >> 4;
            gemm_mma(g_actA + (size_t)ks*64*BB,
                     g_We_h + (size_t)(ks*64)*HH + nt*64, HH, 64,
                     g_part + (size_t)ks*HB + (size_t)nt*4096, me, sA, sW, tid);
        }
        grid_barrier(target);

        // ---- S2r
        for (int idx = gtid; idx < HB; idx += GRID*NTHR){
            float s = b_e_h[idx >> 6];
#pragma unroll
            for (int p = 0; p < 16; p++) s += g_part[(size_t)p*HB + idx];
            g_actB[idx] = tf32r(fmaxf(s, 0.f));
        }
        grid_barrier(target);

        // ---- S3: e partials = e2 @ W_e_out
        {
            int nt = bid & 15, ks = bid >> 4;
            gemm_mma(g_actB + (size_t)ks*64*BB,
                     g_We_out + (size_t)(ks*64)*HH + nt*64, HH, 64,
                     g_part + (size_t)ks*HB + (size_t)nt*4096, me, sA, sW, tid);
        }
        grid_barrier(target);

        // ---- S3r: e exact to skip_out; r = relu(e) rounded -> g_rh[0:HB]
        for (int idx = gtid; idx < HB; idx += GRID*NTHR){
            float s = b_e_out[idx >> 6];
#pragma unroll
            for (int p = 0; p < 16; p++) s += g_part[(size_t)p*HB + idx];
            int nn = idx >> 6, m = idx & 63;
            skip_out[((size_t)m*TTT + t)*HH + nn] = (m < me) ? s : 0.f;
            g_rh[idx] = tf32r(fmaxf(s, 0.f));
        }
        grid_barrier(target);

        // ---- S4: gate partials = [r;h] @ W_cat  (64nt x 4ks, kc=512)
        {
            int nt = bid & 63, ks = bid >> 6;
            gemm_mma(g_rh + (size_t)ks*512*BB,
                     g_Wcat + (size_t)(ks*512)*4096 + nt*64, 4096, 512,
                     g_part + (size_t)ks*(4*HB) + (size_t)nt*4096, me, sA, sW, tid);
        }
        grid_barrier(target);

        // ---- S4r: LSTM pointwise (fp32 state); h rounded -> g_rh[HB:], g_hr
        for (int idx = gtid; idx < HB; idx += GRID*NTHR){
            int j = idx >> 6, m = idx & 63;
            size_t o0 = (size_t)j*BB + m;
            float ig = b_ih[j     ] + b_hh[j     ];
            float fg = b_ih[j+1024] + b_hh[j+1024];
            float gg = b_ih[j+2048] + b_hh[j+2048];
            float og = b_ih[j+3072] + b_hh[j+3072];
#pragma unroll
            for (int p = 0; p < 4; p++){
                const float* gp = g_part + (size_t)p*(4*HB);
                ig += gp[o0               ];
                fg += gp[o0 +     (size_t)HB];
                gg += gp[o0 + 2*(size_t)HB];
                og += gp[o0 + 3*(size_t)HB];
            }
            float cn = sigm(fg)*g_c[idx] + sigm(ig)*tanhf(gg);
            float hn = sigm(og)*tanhf(cn);
            g_c[idx]       = cn;
            float ht = tf32r(hn);
            g_rh[HB + idx] = ht;
            g_hr[idx]      = fmaxf(ht, 0.f);
        }
        grid_barrier(target);

        // ---- S5: d1 partials = relu(h) @ W_o_in
        {
            int nt = bid & 15, ks = bid >> 4;
            gemm_mma(g_hr + (size_t)ks*64*BB,
                     g_Wo_in + (size_t)(ks*64)*HH + nt*64, HH, 64,
                     g_part + (size_t)ks*HB + (size_t)nt*4096, me, sA, sW, tid);
        }
        grid_barrier(target);

        // ---- S5r
        for (int idx = gtid; idx < HB; idx += GRID*NTHR){
            float s = b_o_in[idx >> 6];
#pragma unroll
            for (int p = 0; p < 16; p++) s += g_part[(size_t)p*HB + idx];
            g_actA[idx] = tf32r(fmaxf(s, 0.f));
        }
        grid_barrier(target);

        // ---- S6: d2 partials = d1 @ W_o_h
        {
            int nt = bid & 15, ks = bid >> 4;
            gemm_mma(g_actA + (size_t)ks*64*BB,
                     g_Wo_h + (size_t)(ks*64)*HH + nt*64, HH, 64,
                     g_part + (size_t)ks*HB + (size_t)nt*4096, me, sA, sW, tid);
        }
        grid_barrier(target);

        // ---- S6r
        for (int idx = gtid; idx < HB; idx += GRID*NTHR){
            float s = b_o_h[idx >> 6];
#pragma unroll
            for (int p = 0; p < 16; p++) s += g_part[(size_t)p*HB + idx];
            g_actB[idx] = tf32r(fmaxf(s, 0.f));
        }
        grid_barrier(target);

        // ---- S7: y partials = d2 @ W_o_out  (16 ks, kc=64)
        if (bid < 16){
            gemm_mma(g_actB + (size_t)bid*64*BB,
                     g_Wo_out + (size_t)bid*64*64, OUTD, 64,
                     g_part + (size_t)bid*4096, me, sA, sW, tid);
        }
        grid_barrier(target);

        // ---- S7r: outputs exact; y buffers rounded
        for (int idx = gtid; idx < OUTD*BB; idx += GRID*NTHR){
            float s = b_o_out[idx >> 6];
#pragma unroll
            for (int p = 0; p < 16; p++) s += g_part[(size_t)p*4096 + idx];
            int nn = idx >> 6, m = idx & 63;
            ys_out[((size_t)m*TTT + t)*OUTD + nn] = (m < me) ? s : 0.f;
            float yr = tf32r(s);
            g_y2[idx]           = yr;
            g_y2[OUTD*BB + idx] = yr;
        }
        grid_barrier(target);
    }
}

// ---------------- launch -----------------------------------------------------
extern "C" void kernel_launch(void* const* d_in, const int* in_sizes, int n_in,
                              void* d_out, int out_size)
{
    (void)in_sizes; (void)n_in; (void)out_size;
    const float* x       = (const float*)d_in[0];
    const int*   x_len   = (const int*)  d_in[1];
    const float* y_0     = (const float*)d_in[2];
    const float* y_1     = (const float*)d_in[3];
    const float* W_e_in  = (const float*)d_in[4];
    const float* b_e_in  = (const float*)d_in[5];
    const float* W_e_h   = (const float*)d_in[6];
    const float* b_e_h   = (const float*)d_in[7];
    const float* W_e_out = (const float*)d_in[8];
    const float* b_e_out = (const float*)d_in[9];
    const float* W_ih    = (const float*)d_in[10];
    const float* W_hh    = (const float*)d_in[11];
    const float* b_ih    = (const float*)d_in[12];
    const float* b_hh    = (const float*)d_in[13];
    const float* W_o_in  = (const float*)d_in[14];
    const float* b_o_in  = (const float*)d_in[15];
    const float* W_o_h   = (const float*)d_in[16];
    const float* b_o_h   = (const float*)d_in[17];
    const float* W_o_out = (const float*)d_in[18];
    const float* b_o_out = (const float*)d_in[19];

    init_kernel<<<512, 256>>>(x, y_0, y_1,
                              W_e_in, W_e_h, W_e_out, W_ih, W_hh,
                              W_o_in, W_o_h, W_o_out);
    rnn_kernel<<<GRID, NTHR>>>(x_len,
                               b_e_in, b_e_h, b_e_out,
                               b_ih, b_hh,
                               b_o_in, b_o_h, b_o_out,
                               (float*)d_out);
}